// round 11
// baseline (speedup 1.0000x reference)
#include <cuda_runtime.h>

#define B_ 1024
#define T_ 512
#define C_ 48
#define HALF 24              // i-elements per thread (2-way split of i)
#define WTH 96               // threads per worker (48 states x 2 halves)
#define NWORK 4              // workers per block
#define NTH (WTH * NWORK)    // 384 threads, 12 warps -> 3 per SMSP (balanced)
#define ROW4 (C_ / 4)        // 12 float4 per output row
#define NBLK (148 * 2)       // one resident wave (reg-limited 2 blocks/SM)

__device__ unsigned int g_ctr;                       // work-stealing cursor
__device__ unsigned char g_bp[(size_t)B_ * T_ * C_]; // 25 MB backpointers (L2-resident)

__global__ void reset_ctr_kernel() { g_ctr = 0u; }

__device__ __forceinline__ void wbar(int w) {        // per-worker named barrier
    asm volatile("bar.sync %0, %1;" :: "r"(w + 1), "r"(WTH) : "memory");
}

// monotonic float -> uint32 key (order-preserving)
__device__ __forceinline__ unsigned ordkey(float f) {
    unsigned u = __float_as_uint(f);
    return (u & 0x80000000u) ? ~u : (u | 0x80000000u);
}

// 4 independent 96-thread Viterbi workers per block, each stealing batch
// elements. Worker thread (j,h): j = wtid>>1, h = wtid&1. Streaming
// tournament argmax (strict '>' keeps first-index ties exact). Backpointers
// in gmem; worker warp 0 does the batched chase while warps 1-2 write tail.
__global__ void __launch_bounds__(NTH, 2)
viterbi_kernel(const float* __restrict__ pot,
               const int* __restrict__ seqlen,
               const float* __restrict__ trans,
               float* __restrict__ out)
{
    __shared__ __align__(16) float sc[NWORK][2][C_];
    __shared__ unsigned char tag_sh[NWORK][T_];
    __shared__ int last_tag_sh[NWORK];
    __shared__ unsigned int bidx_sh[NWORK];

    const int tid  = threadIdx.x;
    const int w    = tid / WTH;                      // worker 0..3
    const int wtid = tid - w * WTH;                  // 0..95 within worker
    const int j    = wtid >> 1;                      // state column 0..47
    const int h    = wtid & 1;                       // half 0..1

    // trans rows [h*24, h*24+24) of column j, in registers (work-invariant)
    float tr[HALF];
#pragma unroll
    for (int k = 0; k < HALF; ++k) tr[k] = trans[(h * HALF + k) * C_ + j];

    for (;;) {
        // ---- worker steals next batch element ----
        if (wtid == 0) bidx_sh[w] = atomicAdd(&g_ctr, 1u);
        wbar(w);                                     // also guards smem reuse
        const unsigned b = bidx_sh[w];
        if (b >= B_) return;

        const int L = seqlen[b];                     // 1 <= L < T_
        const float* potb = pot + (size_t)b * T_ * C_;
        unsigned char* bpb = g_bp + (size_t)b * (T_ * C_);

        if (h == 0) sc[w][0][j] = potb[j];           // init score = potentials[:,0]
        wbar(w);

        // ---------------- forward pass ----------------
        int cur = 0;
        float pn1 = (L > 1) ? potb[C_ + j] : 0.0f;
        float pn2 = (L > 2) ? potb[2 * C_ + j] : 0.0f;
        for (int t = 1; t < L; ++t) {
            const float potc = pn1;
            pn1 = pn2;
            if (t + 2 < L) pn2 = potb[(size_t)(t + 2) * C_ + j];

            const float4* sv = (const float4*)(sc[w][cur] + h * HALF);

            // streaming tournament: fold each float4 group to one winner
            float gv[6]; int gi[6];
#pragma unroll
            for (int g = 0; g < 6; ++g) {
                const float4 q = sv[g];
                const int ib = g * 4;
                const float a  = q.x + tr[ib + 0];
                const float b2 = q.y + tr[ib + 1];
                const float c  = q.z + tr[ib + 2];
                const float d  = q.w + tr[ib + 3];
                const float v1 = fmaxf(a, b2);
                const int   i1 = (b2 > a) ? ib + 1 : ib;
                const float v2 = fmaxf(c, d);
                const int   i2 = (d > c) ? ib + 3 : ib + 2;
                gv[g] = fmaxf(v1, v2);
                gi[g] = (v2 > v1) ? i2 : i1;
            }
            // 6 -> 3 -> 1 (strict '>' keeps first index)
            const float u0 = fmaxf(gv[0], gv[1]); const int q0 = (gv[1] > gv[0]) ? gi[1] : gi[0];
            const float u1 = fmaxf(gv[2], gv[3]); const int q1 = (gv[3] > gv[2]) ? gi[3] : gi[2];
            const float u2 = fmaxf(gv[4], gv[5]); const int q2 = (gv[5] > gv[4]) ? gi[5] : gi[4];
            const float w0 = fmaxf(u0, u1);       const int k0 = (u1 > u0) ? q1 : q0;
            const float best = fmaxf(w0, u2);
            const int   lbi  = ((u2 > w0) ? q2 : k0) + h * HALF;

            // combine halves within the lane pair (value desc, then index asc)
            const float ob = __shfl_xor_sync(0xFFFFFFFFu, best, 1);
            const int   oi = __shfl_xor_sync(0xFFFFFFFFu, lbi,  1);
            const bool take_other = (ob > best) || (ob == best && oi < lbi);
            const float wbest = take_other ? ob : best;
            const int   wbi   = take_other ? oi : lbi;

            if (h == 0) {
                bpb[t * C_ + j] = (unsigned char)wbi;   // 16B/warp coalesced STG
                sc[w][cur ^ 1][j] = wbest + potc;
            }
            wbar(w);
            cur ^= 1;
        }

        // ---------------- final argmax (worker warp 0, first-index exact) ----------------
        if (wtid < 32) {
            const float sa = sc[w][cur][wtid];
            const float sb = (wtid < 16) ? sc[w][cur][32 + wtid] : -3.4e38f;
            const unsigned ka = ordkey(sa);
            const unsigned kb = ordkey(sb);
            const unsigned gm = __reduce_max_sync(0xFFFFFFFFu, ka > kb ? ka : kb);
            const unsigned ba = __ballot_sync(0xFFFFFFFFu, ka == gm);
            int tg;
            if (ba) tg = __ffs(ba) - 1;
            else {
                const unsigned bb = __ballot_sync(0xFFFFFFFFu, kb == gm);
                tg = __ffs(bb) - 1 + 32;
            }
            if (wtid == 0) last_tag_sh[w] = tg;
        }
        wbar(w);
        const int lt = last_tag_sh[w];

        float4* ob4 = (float4*)(out + (size_t)b * T_ * C_);

        if (wtid >= 32) {
            // ---- worker warps 1,2: one-hot tail rows t in [L-1, T)
            const int lane64 = wtid - 32;              // 0..63
            const int start = (L - 1) * ROW4;
            for (int idx = start + lane64; idx < T_ * ROW4; idx += 64) {
                const int qq = idx % ROW4;
                const int base = qq * 4;
                float4 vv;
                vv.x = (lt == base + 0) ? 1.0f : 0.0f;
                vv.y = (lt == base + 1) ? 1.0f : 0.0f;
                vv.z = (lt == base + 2) ? 1.0f : 0.0f;
                vv.w = (lt == base + 3) ? 1.0f : 0.0f;
                ob4[idx] = vv;
            }
        } else {
            // ---- worker warp 0: batched bp chase from gmem (L2-resident).
            // Lanes 0..29: lane l holds 16B chunk c=l%3 of row tb-(l/3).
            int tag = lt;
            const int r = wtid / 3;
            const int c = wtid - r * 3;
            for (int tb = L - 1; tb >= 1; tb -= 10) {
                uint4 q = make_uint4(0u, 0u, 0u, 0u);
                const int trow = tb - r;
                if (wtid < 30 && trow >= 1)
                    q = *(const uint4*)(bpb + trow * C_ + c * 16);
                const int kmax = (tb < 10) ? tb : 10;
                for (int k = 0; k < kmax; ++k) {
                    const int src = k * 3 + (tag >> 4);
                    const unsigned w0 = __shfl_sync(0xFFFFFFFFu, q.x, src);
                    const unsigned w1 = __shfl_sync(0xFFFFFFFFu, q.y, src);
                    const unsigned w2 = __shfl_sync(0xFFFFFFFFu, q.z, src);
                    const unsigned w3 = __shfl_sync(0xFFFFFFFFu, q.w, src);
                    const int wsel = (tag >> 2) & 3;
                    const unsigned wlo = (wsel & 1) ? w1 : w0;
                    const unsigned whi = (wsel & 1) ? w3 : w2;
                    const unsigned wv  = (wsel & 2) ? whi : wlo;
                    tag = (int)((wv >> ((tag & 3) * 8)) & 0xFFu);
                    if (wtid == 0) tag_sh[w][(tb - k) - 1] = (unsigned char)tag;
                }
            }
        }
        wbar(w);

        // ---------------- one-hot head rows t in [0, L-1) ----------------
        const int headN = (L - 1) * ROW4;
        for (int idx = wtid; idx < headN; idx += WTH) {
            const int t  = idx / ROW4;
            const int qq = idx - t * ROW4;
            const int tg = tag_sh[w][t];
            const int base = qq * 4;
            float4 vv;
            vv.x = (tg == base + 0) ? 1.0f : 0.0f;
            vv.y = (tg == base + 1) ? 1.0f : 0.0f;
            vv.z = (tg == base + 2) ? 1.0f : 0.0f;
            vv.w = (tg == base + 3) ? 1.0f : 0.0f;
            ob4[idx] = vv;
        }
        // loop: steal next element (barrier at loop head protects smem reuse)
    }
}

extern "C" void kernel_launch(void* const* d_in, const int* in_sizes, int n_in,
                              void* d_out, int out_size)
{
    const float* pot    = (const float*)d_in[0];   // (B, T, C) float32
    const int*   slen   = (const int*)d_in[1];     // (B, 1)    int32
    const float* trans  = (const float*)d_in[2];   // (C, C)    float32
    float*       out    = (float*)d_out;           // (B, T, C) float32

    reset_ctr_kernel<<<1, 1>>>();
    viterbi_kernel<<<NBLK, NTH>>>(pot, slen, trans, out);
}

// round 12
// speedup vs baseline: 1.1647x; 1.1647x over previous
#include <cuda_runtime.h>

#define B_ 1024
#define T_ 512
#define C_ 48
#define WPB 4                      // warps (sequences) per block
#define NTH (WPB * 32)             // 128 threads
#define NBLK (B_ / WPB)            // 256 blocks, exactly one sequence per warp
#define ROW4 (C_ / 4)              // 12 float4 per output row

#define TR_PAD_F 2320              // 48*48 floats + 16 pad (OOB-safe j2 reads)
#define TR_BYTES (TR_PAD_F * 4)    // 9280
#define BP_BYTES (T_ * C_)         // 24576 per warp
#define TAG_BYTES T_               // 512 per warp
#define SMEM_TOTAL (TR_BYTES + WPB * BP_BYTES + WPB * TAG_BYTES)  // 109632

#define NEG_INF __int_as_float(0xff800000)

// monotonic float -> uint32 key (order-preserving) and inverse
__device__ __forceinline__ unsigned ordkey(float f) {
    unsigned u = __float_as_uint(f);
    return (u & 0x80000000u) ? ~u : (u | 0x80000000u);
}
__device__ __forceinline__ float invkey(unsigned k) {
    return (k & 0x80000000u) ? __uint_as_float(k & 0x7FFFFFFFu)
                             : __uint_as_float(~k);
}

// One warp per sequence. Candidate-pruned Viterbi:
// trans in [-0.05, 0.05) => only states with score > max(score) - 0.2 can win
// (0.2 = 2x the exact bound; excluded states are STRICTLY below the winner,
// so values, argmax indices, and first-index tie-breaks are all bit-exact).
// Lane l owns states {l, 32+l (l<16)}. Warp-uniform candidate loop in
// ascending state order with strict '>' reproduces JAX argmax exactly.
__global__ void __launch_bounds__(NTH, 2)
viterbi_kernel(const float* __restrict__ pot,
               const int* __restrict__ seqlen,
               const float* __restrict__ trans,
               float* __restrict__ out)
{
    extern __shared__ unsigned char smem[];
    float* tr_sm = (float*)smem;                               // 48x48 row-major
    const int tid = threadIdx.x;
    const int wid = tid >> 5;
    const int l   = tid & 31;
    unsigned char* bp_w  = smem + TR_BYTES + wid * BP_BYTES;
    unsigned char* tag_w = smem + TR_BYTES + WPB * BP_BYTES + wid * TAG_BYTES;

    // block-cooperative load of transitions (+ zero pad)
    for (int i = tid; i < C_ * C_; i += NTH) tr_sm[i] = trans[i];
    for (int i = C_ * C_ + tid; i < TR_PAD_F; i += NTH) tr_sm[i] = 0.0f;
    __syncthreads();

    const int b = blockIdx.x * WPB + wid;
    const int L = seqlen[b];                                   // 1 <= L < T_
    const float* potb = pot + (size_t)b * T_ * C_;

    // score registers: s1 = score[l], s2 = score[32+l] (l<16)
    float s1 = potb[l];
    float s2 = (l < 16) ? potb[32 + l] : NEG_INF;

    // 2-deep potential prefetch
    float p1a = 0.f, p1b = 0.f, p2a = 0.f, p2b = 0.f;
    if (L > 1) { p1a = potb[C_ + l];     if (l < 16) p1b = potb[C_ + 32 + l]; }
    if (L > 2) { p2a = potb[2 * C_ + l]; if (l < 16) p2b = potb[2 * C_ + 32 + l]; }

    // ---------------- forward pass ----------------
    for (int t = 1; t < L; ++t) {
        const float pa = p1a, pb = p1b;
        p1a = p2a; p1b = p2b;
        if (t + 2 < L) {
            p2a = potb[(size_t)(t + 2) * C_ + l];
            if (l < 16) p2b = potb[(size_t)(t + 2) * C_ + 32 + l];
        }

        // step max + candidate masks
        const unsigned k1 = ordkey(s1);
        const unsigned k2 = (l < 16) ? ordkey(s2) : 0u;
        const unsigned gm = __reduce_max_sync(0xFFFFFFFFu, k1 > k2 ? k1 : k2);
        const float thr = invkey(gm) - 0.2f;
        unsigned m1 = __ballot_sync(0xFFFFFFFFu, s1 > thr);
        unsigned m2 = __ballot_sync(0xFFFFFFFFu, (l < 16) && (s2 > thr));

        // candidate loop (warp-uniform), ascending state index, strict '>'
        float v1 = NEG_INF, v2 = NEG_INF;
        int   i1 = 0,       i2 = 0;
        while (m1) {
            const int c = __ffs(m1) - 1; m1 &= m1 - 1;
            const float sc = __shfl_sync(0xFFFFFFFFu, s1, c);
            const float c1 = sc + tr_sm[c * C_ + l];
            const float c2 = sc + tr_sm[c * C_ + 32 + l];
            if (c1 > v1) { v1 = c1; i1 = c; }
            if (c2 > v2) { v2 = c2; i2 = c; }
        }
        while (m2) {
            const int c = __ffs(m2) - 1; m2 &= m2 - 1;
            const float sc = __shfl_sync(0xFFFFFFFFu, s2, c);
            const int  ci = c + 32;
            const float c1 = sc + tr_sm[ci * C_ + l];
            const float c2 = sc + tr_sm[ci * C_ + 32 + l];
            if (c1 > v1) { v1 = c1; i1 = ci; }
            if (c2 > v2) { v2 = c2; i2 = ci; }
        }

        bp_w[t * C_ + l] = (unsigned char)i1;
        if (l < 16) bp_w[t * C_ + 32 + l] = (unsigned char)i2;
        s1 = v1 + pa;
        if (l < 16) s2 = v2 + pb;
    }

    // ---------------- final argmax (first-index exact) ----------------
    {
        const unsigned k1 = ordkey(s1);
        const unsigned k2 = (l < 16) ? ordkey(s2) : 0u;
        const unsigned gm = __reduce_max_sync(0xFFFFFFFFu, k1 > k2 ? k1 : k2);
        const unsigned b1 = __ballot_sync(0xFFFFFFFFu, k1 == gm);
        int lt;
        if (b1) lt = __ffs(b1) - 1;
        else {
            const unsigned b2 = __ballot_sync(0xFFFFFFFFu, (l < 16) && (k2 == gm));
            lt = __ffs(b2) - 1 + 32;
        }

        __syncwarp();                                  // bp writes visible to all lanes

        // ---------------- backpointer chase (broadcast LDS, converged) ----------------
        int tag = lt;
        for (int t = L - 1; t >= 1; --t) {
            tag = bp_w[t * C_ + tag];
            if (l == 0) tag_w[t - 1] = (unsigned char)tag;
        }
        __syncwarp();                                  // tag_w visible

        // ---------------- fused one-hot output ----------------
        float4* ob4 = (float4*)(out + (size_t)b * T_ * C_);
        for (int idx = l; idx < T_ * ROW4; idx += 32) {
            const int t  = idx / ROW4;
            const int q  = idx - t * ROW4;
            const int tg = (t >= L - 1) ? lt : (int)tag_w[t];
            const int base = q * 4;
            float4 w;
            w.x = (tg == base + 0) ? 1.0f : 0.0f;
            w.y = (tg == base + 1) ? 1.0f : 0.0f;
            w.z = (tg == base + 2) ? 1.0f : 0.0f;
            w.w = (tg == base + 3) ? 1.0f : 0.0f;
            ob4[idx] = w;
        }
    }
}

extern "C" void kernel_launch(void* const* d_in, const int* in_sizes, int n_in,
                              void* d_out, int out_size)
{
    const float* pot    = (const float*)d_in[0];   // (B, T, C) float32
    const int*   slen   = (const int*)d_in[1];     // (B, 1)    int32
    const float* trans  = (const float*)d_in[2];   // (C, C)    float32
    float*       out    = (float*)d_out;           // (B, T, C) float32

    // Opt in to >48KB dynamic shared memory (107 KB/block -> 2 blocks/SM).
    static int attr_done = 0;
    if (!attr_done) {
        cudaFuncSetAttribute(viterbi_kernel,
                             cudaFuncAttributeMaxDynamicSharedMemorySize,
                             SMEM_TOTAL);
        attr_done = 1;
    }

    viterbi_kernel<<<NBLK, NTH, SMEM_TOTAL>>>(pot, slen, trans, out);
}